// round 2
// baseline (speedup 1.0000x reference)
#include <cuda_runtime.h>
#include <cstdint>

// Problem constants
#define BATCH 32
#define CH    256
#define HH    56
#define WW    56
#define HW    (HH*WW)              // 3136
#define NPIX  (BATCH*HW)           // 100352
#define NELEM (BATCH*CH*HW)        // 25690112
#define NWORD 8                    // 256 channels / 32
#define KTAPS 9
#define EPSBN 1e-5f

// Conv tiling
#define TH 8
#define TW 28
#define NTHREADS (TH*TW)           // 224
#define OPB 16                     // output channels per block
#define OSPLIT (CH/OPB)            // 16

// -------------------- device scratch (static, no allocations) --------------------
__device__ __align__(16) float    g_y[NELEM];                   // sub-block1 output
__device__ __align__(16) uint32_t g_abits1[NPIX*NWORD];         // packed sign(x+shA): [B][H][W][8]
__device__ __align__(16) uint32_t g_abits2[NPIX*NWORD];         // packed sign(x+shB)
__device__ __align__(16) uint32_t g_wbits[2][CH*KTAPS*NWORD];   // packed sign(w): [o][tap][8]
__device__ int   g_popcw[2][CH*KTAPS];                          // popcount of w bits per (o,tap)
__device__ float g_k1[2][CH], g_k2[2][CH], g_c0[2][CH];

// -------------------- prep: weights -> bits, popcw, fused epilogue coeffs --------------------
__global__ void prep_kernel(const float* __restrict__ w,
                            const float* __restrict__ sc,
                            const float* __restrict__ g,
                            const float* __restrict__ beta,
                            const float* __restrict__ mean,
                            const float* __restrict__ var,
                            int blk)
{
    const int o   = blockIdx.x;
    const int tid = threadIdx.x;          // 128 threads
    __shared__ float red[128];
    __shared__ int   tapc[KTAPS];

    float s = 0.f;
    const float* wo = w + o * (CH * KTAPS);
    for (int i = tid; i < CH * KTAPS; i += 128) s += fabsf(wo[i]);
    red[tid] = s;
    __syncthreads();
    for (int st = 64; st > 0; st >>= 1) {
        if (tid < st) red[tid] += red[tid + st];
        __syncthreads();
    }
    if (tid < KTAPS) tapc[tid] = 0;
    __syncthreads();

    if (tid < KTAPS * NWORD) {
        const int tap  = tid / NWORD;
        const int word = tid % NWORD;
        uint32_t bits = 0;
        #pragma unroll
        for (int j = 0; j < 32; j++) {
            const int c = word * 32 + j;
            const float wv = w[(o * CH + c) * KTAPS + tap];
            bits |= (uint32_t)(wv > 0.f) << j;
        }
        g_wbits[blk][(o * KTAPS + tap) * NWORD + word] = bits;
        atomicAdd(&tapc[tap], __popc(bits));
    }
    __syncthreads();
    if (tid < KTAPS) g_popcw[blk][o * KTAPS + tid] = tapc[tid];

    if (tid == 0) {
        const float alpha = red[0] / (float)(CH * KTAPS);
        const float istd  = rsqrtf(var[o] + EPSBN);
        const float k1 = alpha * istd * g[o];
        g_k1[blk][o] = k1;
        g_k2[blk][o] = sc[o] * k1;
        g_c0[blk][o] = beta[o] - mean[o] * istd * g[o];
    }
}

// -------------------- pack: float NCHW -> channel-packed sign bits [B][H][W][8] --------------------
__global__ void pack_kernel(const float* __restrict__ in,
                            const float* __restrict__ shA,
                            const float* __restrict__ shB)
{
    __shared__ float s1[CH], s2[CH];
    const int tid = threadIdx.x;
    s1[tid] = shA[tid];
    s2[tid] = shB[tid];
    __syncthreads();

    const int pix = blockIdx.x * blockDim.x + tid;   // 0..NPIX-1
    if (pix >= NPIX) return;
    const int b  = pix / HW;
    const int hw = pix % HW;
    const int base = b * (CH * HW) + hw;

    #pragma unroll
    for (int k = 0; k < NWORD; k++) {
        uint32_t b1 = 0, b2 = 0;
        #pragma unroll
        for (int j = 0; j < 32; j++) {
            const int c = k * 32 + j;
            const float v = in[base + c * HW];
            b1 |= (uint32_t)(v + s1[c] > 0.f) << j;
            b2 |= (uint32_t)(v + s2[c] > 0.f) << j;
        }
        g_abits1[pix * NWORD + k] = b1;
        g_abits2[pix * NWORD + k] = b2;
    }
}

// -------------------- conv: XNOR-popcount, dual activation, packed acc, fused epilogue --------------------
__device__ __forceinline__ int popc8(const uint4& al, const uint4& ah, const uint4& wl, const uint4& wh) {
    return __popc(al.x ^ wl.x) + __popc(al.y ^ wl.y) + __popc(al.z ^ wl.z) + __popc(al.w ^ wl.w)
         + __popc(ah.x ^ wh.x) + __popc(ah.y ^ wh.y) + __popc(ah.z ^ wh.z) + __popc(ah.w ^ wh.w);
}

__global__ __launch_bounds__(NTHREADS, 4)
void conv_kernel(int blk,
                 const float* __restrict__ residual,
                 float* __restrict__ out)
{
    // smem: weights [OPB][9][8] words (4.6KB) + acts [2][10 rows][2 halves][30 cols] uint4 (19.2KB)
    __shared__ __align__(16) uint32_t wsm[OPB * KTAPS * NWORD];
    __shared__ __align__(16) uint4    as4[2 * 10 * 2 * 30];

    const int tid    = threadIdx.x;
    const int colT   = blockIdx.x & 1;           // 0..1
    const int rowT   = blockIdx.x >> 1;          // 0..6
    const int b      = blockIdx.y;               // 0..31
    const int oBase  = blockIdx.z * OPB;         // 0,16,...,240
    const int h0     = rowT * TH;
    const int w0     = colT * TW;

    // load weight bits for this o-range (288 uint4)
    {
        const uint4* wsrc = reinterpret_cast<const uint4*>(&g_wbits[blk][oBase * KTAPS * NWORD]);
        uint4* wdst = reinterpret_cast<uint4*>(wsm);
        for (int i = tid; i < OPB * KTAPS * 2; i += NTHREADS) wdst[i] = wsrc[i];
    }

    // load activation halo tiles (zero-filled out-of-image)
    {
        const uint4* ab1 = reinterpret_cast<const uint4*>(g_abits1);
        const uint4* ab2 = reinterpret_cast<const uint4*>(g_abits2);
        for (int idx = tid; idx < 2 * 300; idx += NTHREADS) {
            const int a    = idx / 300;
            const int cell = idx % 300;
            const int rr = cell / 30;
            const int cc = cell % 30;
            const int gh = h0 - 1 + rr;
            const int gw = w0 - 1 + cc;
            uint4 lo = make_uint4(0u, 0u, 0u, 0u);
            uint4 hi = make_uint4(0u, 0u, 0u, 0u);
            if (gh >= 0 && gh < HH && gw >= 0 && gw < WW) {
                const uint4* src = (a == 0) ? ab1 : ab2;
                const int gidx = ((b * HH + gh) * WW + gw) * 2;
                lo = src[gidx];
                hi = src[gidx + 1];
            }
            const int dbase = a * 600 + rr * 60 + cc;
            as4[dbase]      = lo;
            as4[dbase + 30] = hi;
        }
    }
    __syncthreads();

    const int r = tid / TW;
    const int c = tid % TW;
    const int h = h0 + r;
    const int w = w0 + c;

    // out-of-bounds tap mask for padding correction
    int oobmask = 0;
    #pragma unroll
    for (int tap = 0; tap < KTAPS; tap++) {
        const int dh = tap / 3 - 1, dw = tap % 3 - 1;
        if (h + dh < 0 || h + dh >= HH || w + dw < 0 || w + dw >= WW) oobmask |= 1 << tap;
    }

    const uint4* wsm4 = reinterpret_cast<const uint4*>(wsm);

    // Packed accumulators: acc1 (act1) in low 16 bits, acc2 (act2) in high 16 bits.
    // Max value 9*256 = 2304 < 65536, no overflow.
    int acc[OPB];
    #pragma unroll
    for (int j = 0; j < OPB; j++) acc[j] = 0;

    // tap loops kept rolled to bound I$ footprint; inner o-loop fully unrolled
    for (int dr = 0; dr < 3; dr++) {
        for (int dc = 0; dc < 3; dc++) {
            const int tap = dr * 3 + dc;
            const int ab  = (r + dr) * 60 + (c + dc);
            const uint4 a1l = as4[ab];
            const uint4 a1h = as4[ab + 30];
            const uint4 a2l = as4[ab + 600];
            const uint4 a2h = as4[ab + 630];
            #pragma unroll
            for (int j = 0; j < OPB; j++) {
                const int wi = (j * KTAPS + tap) * 2;
                const uint4 wl = wsm4[wi];
                const uint4 wh = wsm4[wi + 1];
                const int p1 = popc8(a1l, a1h, wl, wh);
                const int p2 = popc8(a2l, a2h, wl, wh);
                acc[j] = p2 * 65536 + (acc[j] + p1);   // IMAD (fma pipe) + IADD3 (alu pipe)
            }
        }
    }

    const float* k1p = g_k1[blk];
    const float* k2p = g_k2[blk];
    const float* c0p = g_c0[blk];
    const int*   pcw = g_popcw[blk];

    #pragma unroll
    for (int j = 0; j < OPB; j++) {
        const int o = oBase + j;
        int corr = 0;
        if (oobmask) {
            #pragma unroll
            for (int tap = 0; tap < KTAPS; tap++)
                if ((oobmask >> tap) & 1)
                    corr += CH - 2 * __ldg(&pcw[o * KTAPS + tap]);
        }
        const int a1 = acc[j] & 0xFFFF;
        const int a2 = acc[j] >> 16;
        const int d1 = CH * KTAPS - 2 * a1 - corr;
        const int d2 = CH * KTAPS - 2 * a2 - corr;
        const int oidx = ((b * CH + o) * HH + h) * WW + w;
        float val = __ldg(&k1p[o]) * (float)d1
                  + __ldg(&k2p[o]) * (float)d2
                  + __ldg(&c0p[o])
                  + residual[oidx];
        val = fminf(fmaxf(val, -1.0f), 1.0f);
        out[oidx] = val;
    }
}

// -------------------- launch --------------------
extern "C" void kernel_launch(void* const* d_in, const int* in_sizes, int n_in,
                              void* d_out, int out_size)
{
    const float* x    = (const float*)d_in[0];
    const float* sh11 = (const float*)d_in[1];
    const float* sh12 = (const float*)d_in[2];
    const float* w1   = (const float*)d_in[3];
    const float* sc1  = (const float*)d_in[4];
    const float* g1   = (const float*)d_in[5];
    const float* b1   = (const float*)d_in[6];
    const float* m1   = (const float*)d_in[7];
    const float* v1   = (const float*)d_in[8];
    const float* sh21 = (const float*)d_in[9];
    const float* sh22 = (const float*)d_in[10];
    const float* w2   = (const float*)d_in[11];
    const float* sc2  = (const float*)d_in[12];
    const float* g2   = (const float*)d_in[13];
    const float* b2   = (const float*)d_in[14];
    const float* m2   = (const float*)d_in[15];
    const float* v2   = (const float*)d_in[16];
    float* outp = (float*)d_out;

    void* yp_raw = nullptr;
    cudaGetSymbolAddress(&yp_raw, g_y);
    float* yp = (float*)yp_raw;

    prep_kernel<<<CH, 128>>>(w1, sc1, g1, b1, m1, v1, 0);
    prep_kernel<<<CH, 128>>>(w2, sc2, g2, b2, m2, v2, 1);

    dim3 cgrid(14, BATCH, OSPLIT);   // 14 spatial tiles x 32 batch x 16 o-splits

    pack_kernel<<<(NPIX + 255) / 256, 256>>>(x, sh11, sh12);
    conv_kernel<<<cgrid, NTHREADS>>>(0, x, yp);

    pack_kernel<<<(NPIX + 255) / 256, 256>>>(yp, sh21, sh22);
    conv_kernel<<<cgrid, NTHREADS>>>(1, yp, outp);
}

// round 3
// speedup vs baseline: 1.5799x; 1.5799x over previous
#include <cuda_runtime.h>
#include <cstdint>

// Problem constants
#define BATCH 32
#define CH    256
#define HH    56
#define WW    56
#define HW    (HH*WW)              // 3136
#define NPIX  (BATCH*HW)           // 100352
#define NELEM (BATCH*CH*HW)        // 25690112
#define NWORD 8                    // 256 channels / 32
#define KTAPS 9
#define EPSBN 1e-5f

// Conv tiling (round-1 geometry: low halo traffic)
#define TH 8
#define TW 28
#define NTHREADS (TH*TW)           // 224
#define OSPLIT 4
#define OPB (CH/OSPLIT)            // 64 output channels per block
#define OG  2                      // o-channels per register group

// -------------------- device scratch (static, no allocations) --------------------
__device__ __align__(16) float    g_y[NELEM];                   // sub-block1 output
__device__ __align__(16) uint32_t g_abits1[NPIX*NWORD];         // packed sign(x+shA): [B][H][W][8]
__device__ __align__(16) uint32_t g_abits2[NPIX*NWORD];         // packed sign(x+shB)
__device__ __align__(16) uint32_t g_wbits[2][CH*KTAPS*NWORD];   // packed sign(w): [o][tap][8]
__device__ int   g_popcw[2][CH*KTAPS];                          // popcount of w bits per (o,tap)
__device__ float g_k1[2][CH], g_k2[2][CH], g_c0[2][CH];

// -------------------- prep: weights -> bits, popcw, fused epilogue coeffs --------------------
__global__ void prep_kernel(const float* __restrict__ w,
                            const float* __restrict__ sc,
                            const float* __restrict__ g,
                            const float* __restrict__ beta,
                            const float* __restrict__ mean,
                            const float* __restrict__ var,
                            int blk)
{
    const int o   = blockIdx.x;
    const int tid = threadIdx.x;          // 128 threads
    __shared__ float red[128];
    __shared__ int   tapc[KTAPS];

    float s = 0.f;
    const float* wo = w + o * (CH * KTAPS);
    for (int i = tid; i < CH * KTAPS; i += 128) s += fabsf(wo[i]);
    red[tid] = s;
    __syncthreads();
    for (int st = 64; st > 0; st >>= 1) {
        if (tid < st) red[tid] += red[tid + st];
        __syncthreads();
    }
    if (tid < KTAPS) tapc[tid] = 0;
    __syncthreads();

    if (tid < KTAPS * NWORD) {
        const int tap  = tid / NWORD;
        const int word = tid % NWORD;
        uint32_t bits = 0;
        #pragma unroll
        for (int j = 0; j < 32; j++) {
            const int c = word * 32 + j;
            const float wv = w[(o * CH + c) * KTAPS + tap];
            bits |= (uint32_t)(wv > 0.f) << j;
        }
        g_wbits[blk][(o * KTAPS + tap) * NWORD + word] = bits;
        atomicAdd(&tapc[tap], __popc(bits));
    }
    __syncthreads();
    if (tid < KTAPS) g_popcw[blk][o * KTAPS + tid] = tapc[tid];

    if (tid == 0) {
        const float alpha = red[0] / (float)(CH * KTAPS);
        const float istd  = rsqrtf(var[o] + EPSBN);
        const float k1 = alpha * istd * g[o];
        g_k1[blk][o] = k1;
        g_k2[blk][o] = sc[o] * k1;
        g_c0[blk][o] = beta[o] - mean[o] * istd * g[o];
    }
}

// -------------------- pack: float NCHW -> channel-packed sign bits [B][H][W][8] --------------------
__global__ void pack_kernel(const float* __restrict__ in,
                            const float* __restrict__ shA,
                            const float* __restrict__ shB)
{
    __shared__ float s1[CH], s2[CH];
    const int tid = threadIdx.x;
    s1[tid] = shA[tid];
    s2[tid] = shB[tid];
    __syncthreads();

    const int pix = blockIdx.x * blockDim.x + tid;   // 0..NPIX-1
    if (pix >= NPIX) return;
    const int b  = pix / HW;
    const int hw = pix % HW;
    const int base = b * (CH * HW) + hw;

    #pragma unroll
    for (int k = 0; k < NWORD; k++) {
        uint32_t b1 = 0, b2 = 0;
        #pragma unroll
        for (int j = 0; j < 32; j++) {
            const int c = k * 32 + j;
            const float v = in[base + c * HW];
            b1 |= (uint32_t)(v + s1[c] > 0.f) << j;
            b2 |= (uint32_t)(v + s2[c] > 0.f) << j;
        }
        g_abits1[pix * NWORD + k] = b1;
        g_abits2[pix * NWORD + k] = b2;
    }
}

// -------------------- CSA popcount: sum popc of 8 words with only 4 POPCs --------------------
__device__ __forceinline__ void fa3(uint32_t a, uint32_t b, uint32_t c,
                                    uint32_t& s, uint32_t& cy) {
    s  = a ^ b ^ c;                       // LOP3 0x96
    cy = (a & b) | (c & (a ^ b));         // LOP3 0xE8 (majority)
}

__device__ __forceinline__ int csa_popc8(uint32_t x0, uint32_t x1, uint32_t x2, uint32_t x3,
                                         uint32_t x4, uint32_t x5, uint32_t x6, uint32_t x7) {
    uint32_t s1a, c2a, s1b, c2b, s1c, c2c, s2, c4;
    fa3(x0, x1, x2, s1a, c2a);
    fa3(x3, x4, x5, s1b, c2b);
    fa3(s1a, s1b, x6, s1c, c2c);
    fa3(c2a, c2b, c2c, s2, c4);
    // sum = s1c + x7 + 2*(c2a+c2b+c2c) = s1c + x7 + 2*s2 + 4*c4
    return __popc(s1c) + __popc(x7) + 2 * __popc(s2) + 4 * __popc(c4);
}

// -------------------- conv: XNOR + CSA popcount, dual activation, fused epilogue --------------------
__global__ __launch_bounds__(NTHREADS, 4)
void conv_kernel(int blk,
                 const float* __restrict__ residual,
                 float* __restrict__ out)
{
    // smem: weights [OPB][9][8] words (18KB) + acts [2][10 rows][2 halves][30 cols] uint4 (19.2KB)
    __shared__ __align__(16) uint32_t wsm[OPB * KTAPS * NWORD];
    __shared__ __align__(16) uint4    as4[2 * 10 * 2 * 30];

    const int tid    = threadIdx.x;
    const int colT   = blockIdx.x & 1;           // 0..1
    const int rowT   = blockIdx.x >> 1;          // 0..6
    const int b      = blockIdx.y;               // 0..31
    const int oBase  = blockIdx.z * OPB;         // 0,64,128,192
    const int h0     = rowT * TH;
    const int w0     = colT * TW;

    // load weight bits for this o-range (1152 uint4)
    {
        const uint4* wsrc = reinterpret_cast<const uint4*>(&g_wbits[blk][oBase * KTAPS * NWORD]);
        uint4* wdst = reinterpret_cast<uint4*>(wsm);
        for (int i = tid; i < OPB * KTAPS * 2; i += NTHREADS) wdst[i] = wsrc[i];
    }

    // load activation halo tiles (zero-filled out-of-image)
    {
        const uint4* ab1 = reinterpret_cast<const uint4*>(g_abits1);
        const uint4* ab2 = reinterpret_cast<const uint4*>(g_abits2);
        for (int idx = tid; idx < 2 * 300; idx += NTHREADS) {
            const int a    = idx / 300;
            const int cell = idx % 300;
            const int rr = cell / 30;
            const int cc = cell % 30;
            const int gh = h0 - 1 + rr;
            const int gw = w0 - 1 + cc;
            uint4 lo = make_uint4(0u, 0u, 0u, 0u);
            uint4 hi = make_uint4(0u, 0u, 0u, 0u);
            if (gh >= 0 && gh < HH && gw >= 0 && gw < WW) {
                const uint4* src = (a == 0) ? ab1 : ab2;
                const int gidx = ((b * HH + gh) * WW + gw) * 2;
                lo = src[gidx];
                hi = src[gidx + 1];
            }
            const int dbase = a * 600 + rr * 60 + cc;
            as4[dbase]      = lo;
            as4[dbase + 30] = hi;
        }
    }
    __syncthreads();

    const int r = tid / TW;
    const int c = tid % TW;
    const int h = h0 + r;
    const int w = w0 + c;

    // out-of-bounds tap mask for padding correction
    int oobmask = 0;
    #pragma unroll
    for (int tap = 0; tap < KTAPS; tap++) {
        const int dh = tap / 3 - 1, dw = tap % 3 - 1;
        if (h + dh < 0 || h + dh >= HH || w + dw < 0 || w + dw >= WW) oobmask |= 1 << tap;
    }

    const uint4* wsm4 = reinterpret_cast<const uint4*>(wsm);
    const float* k1p = g_k1[blk];
    const float* k2p = g_k2[blk];
    const float* c0p = g_c0[blk];
    const int*   pcw = g_popcw[blk];

    for (int og = 0; og < OPB / OG; og++) {       // 32 iterations, 2 o each
        int acc1[OG] = {0, 0};
        int acc2[OG] = {0, 0};

        #pragma unroll
        for (int dr = 0; dr < 3; dr++) {
            #pragma unroll
            for (int dc = 0; dc < 3; dc++) {
                const int tap = dr * 3 + dc;
                const int ab  = (r + dr) * 60 + (c + dc);
                const uint4 a1l = as4[ab];
                const uint4 a1h = as4[ab + 30];
                const uint4 a2l = as4[ab + 600];
                const uint4 a2h = as4[ab + 630];
                #pragma unroll
                for (int j = 0; j < OG; j++) {
                    const int wi = ((og * OG + j) * KTAPS + tap) * 2;
                    const uint4 wl = wsm4[wi];
                    const uint4 wh = wsm4[wi + 1];
                    acc1[j] += csa_popc8(a1l.x ^ wl.x, a1l.y ^ wl.y, a1l.z ^ wl.z, a1l.w ^ wl.w,
                                         a1h.x ^ wh.x, a1h.y ^ wh.y, a1h.z ^ wh.z, a1h.w ^ wh.w);
                    acc2[j] += csa_popc8(a2l.x ^ wl.x, a2l.y ^ wl.y, a2l.z ^ wl.z, a2l.w ^ wl.w,
                                         a2h.x ^ wh.x, a2h.y ^ wh.y, a2h.z ^ wh.z, a2h.w ^ wh.w);
                }
            }
        }

        #pragma unroll
        for (int j = 0; j < OG; j++) {
            const int o = oBase + og * OG + j;
            int corr = 0;
            if (oobmask) {
                #pragma unroll
                for (int tap = 0; tap < KTAPS; tap++)
                    if ((oobmask >> tap) & 1)
                        corr += CH - 2 * __ldg(&pcw[o * KTAPS + tap]);
            }
            const int d1 = CH * KTAPS - 2 * acc1[j] - corr;
            const int d2 = CH * KTAPS - 2 * acc2[j] - corr;
            const int oidx = ((b * CH + o) * HH + h) * WW + w;
            float val = __ldg(&k1p[o]) * (float)d1
                      + __ldg(&k2p[o]) * (float)d2
                      + __ldg(&c0p[o])
                      + residual[oidx];
            val = fminf(fmaxf(val, -1.0f), 1.0f);
            out[oidx] = val;
        }
    }
}

// -------------------- launch --------------------
extern "C" void kernel_launch(void* const* d_in, const int* in_sizes, int n_in,
                              void* d_out, int out_size)
{
    const float* x    = (const float*)d_in[0];
    const float* sh11 = (const float*)d_in[1];
    const float* sh12 = (const float*)d_in[2];
    const float* w1   = (const float*)d_in[3];
    const float* sc1  = (const float*)d_in[4];
    const float* g1   = (const float*)d_in[5];
    const float* b1   = (const float*)d_in[6];
    const float* m1   = (const float*)d_in[7];
    const float* v1   = (const float*)d_in[8];
    const float* sh21 = (const float*)d_in[9];
    const float* sh22 = (const float*)d_in[10];
    const float* w2   = (const float*)d_in[11];
    const float* sc2  = (const float*)d_in[12];
    const float* g2   = (const float*)d_in[13];
    const float* b2   = (const float*)d_in[14];
    const float* m2   = (const float*)d_in[15];
    const float* v2   = (const float*)d_in[16];
    float* outp = (float*)d_out;

    void* yp_raw = nullptr;
    cudaGetSymbolAddress(&yp_raw, g_y);
    float* yp = (float*)yp_raw;

    prep_kernel<<<CH, 128>>>(w1, sc1, g1, b1, m1, v1, 0);
    prep_kernel<<<CH, 128>>>(w2, sc2, g2, b2, m2, v2, 1);

    dim3 cgrid(14, BATCH, OSPLIT);   // 14 spatial tiles x 32 batch x 4 o-splits

    pack_kernel<<<(NPIX + 255) / 256, 256>>>(x, sh11, sh12);
    conv_kernel<<<cgrid, NTHREADS>>>(0, x, yp);

    pack_kernel<<<(NPIX + 255) / 256, 256>>>(yp, sh21, sh22);
    conv_kernel<<<cgrid, NTHREADS>>>(1, yp, outp);
}